// round 1
// baseline (speedup 1.0000x reference)
#include <cuda_runtime.h>
#include <math.h>

// ---------------------------------------------------------------------------
// Attention_64037962383812: B=8, L=2048, D=512, fp32.
//   q = input @ wq^T + bq ; k = states @ wk^T + bk ; v = states @ wv^T + bv
//   S = (q @ k^T) / sqrt(D), masked ; P = softmax_k(S) ; out = P @ v
// Round-0 baseline: fully fp32, materialized pipeline:
//   [gemm NT x3] -> [gemm NT batched (scores)] -> [masked softmax] -> [gemm NN batched]
// Scratch in __device__ globals (no allocations).
// ---------------------------------------------------------------------------

#define BATCH 8
#define SEQ   2048
#define DIM   512

#define BM 64
#define BN 64
#define BK 32
#define SPAD 68   // padded smem row stride (floats); 68*4=272 bytes, %16==0 -> LDS.128 ok

__device__ float g_q[(size_t)BATCH * SEQ * DIM];
__device__ float g_k[(size_t)BATCH * SEQ * DIM];
__device__ float g_v[(size_t)BATCH * SEQ * DIM];
__device__ float g_s[(size_t)BATCH * SEQ * SEQ];

// C[M,N] = scale * (A[M,K] @ B') + bias
//   B_KMAJOR = true : B is [N,K] row-major (i.e. C = A @ B^T)   -- used for QKV, scores
//   B_KMAJOR = false: B is [K,N] row-major (i.e. C = A @ B)     -- used for P @ V
// Batched via blockIdx.z with element strides sA/sB/sC.
template <bool B_KMAJOR>
__global__ void __launch_bounds__(256, 2)
gemm64(const float* __restrict__ Ab, const float* __restrict__ Bb,
       const float* __restrict__ bias, float* __restrict__ Cb,
       int M, int N, int K,
       size_t sA, size_t sB, size_t sC, float scale)
{
    __shared__ float As[BK][SPAD];
    __shared__ float Bs[BK][SPAD];

    const int bz = blockIdx.z;
    const float* A = Ab + (size_t)bz * sA;
    const float* B = Bb + (size_t)bz * sB;
    float*       C = Cb + (size_t)bz * sC;

    const int m0 = blockIdx.y * BM;
    const int n0 = blockIdx.x * BN;
    const int tid = threadIdx.x;
    const int tx = tid & 15;       // 0..15 -> output cols tx*4..tx*4+3
    const int ty = tid >> 4;       // 0..15 -> output rows ty*4..ty*4+3

    float acc[4][4] = {};

    for (int k0 = 0; k0 < K; k0 += BK) {
        // --- load A tile (BM x BK), store transposed As[k][row] ---
        #pragma unroll
        for (int i = 0; i < 2; i++) {
            int f   = tid + 256 * i;           // 0..511 (64 rows * 8 float4)
            int row = f >> 3;
            int kq  = (f & 7) << 2;
            float4 t = *(const float4*)(A + (size_t)(m0 + row) * K + k0 + kq);
            As[kq + 0][row] = t.x;
            As[kq + 1][row] = t.y;
            As[kq + 2][row] = t.z;
            As[kq + 3][row] = t.w;
        }
        // --- load B tile -> Bs[k][col] ---
        if (B_KMAJOR) {
            #pragma unroll
            for (int i = 0; i < 2; i++) {
                int f   = tid + 256 * i;
                int col = f >> 3;
                int kq  = (f & 7) << 2;
                float4 t = *(const float4*)(B + (size_t)(n0 + col) * K + k0 + kq);
                Bs[kq + 0][col] = t.x;
                Bs[kq + 1][col] = t.y;
                Bs[kq + 2][col] = t.z;
                Bs[kq + 3][col] = t.w;
            }
        } else {
            #pragma unroll
            for (int i = 0; i < 2; i++) {
                int f  = tid + 256 * i;        // 32 k-rows * 16 float4 cols
                int kk = f >> 4;
                int cq = (f & 15) << 2;
                float4 t = *(const float4*)(B + (size_t)(k0 + kk) * N + n0 + cq);
                *(float4*)&Bs[kk][cq] = t;
            }
        }
        __syncthreads();

        #pragma unroll
        for (int kk = 0; kk < BK; kk++) {
            float4 av = *(const float4*)&As[kk][ty * 4];
            float4 bv = *(const float4*)&Bs[kk][tx * 4];
            float a[4] = {av.x, av.y, av.z, av.w};
            float b[4] = {bv.x, bv.y, bv.z, bv.w};
            #pragma unroll
            for (int i = 0; i < 4; i++)
                #pragma unroll
                for (int j = 0; j < 4; j++)
                    acc[i][j] += a[i] * b[j];
        }
        __syncthreads();
    }

    // --- epilogue: scale + bias, float4 stores ---
    const int col = n0 + tx * 4;
    float4 bvec = make_float4(0.f, 0.f, 0.f, 0.f);
    if (bias) bvec = *(const float4*)(bias + col);
    #pragma unroll
    for (int i = 0; i < 4; i++) {
        int row = m0 + ty * 4 + i;
        float4 o;
        o.x = acc[i][0] * scale + bvec.x;
        o.y = acc[i][1] * scale + bvec.y;
        o.z = acc[i][2] * scale + bvec.z;
        o.w = acc[i][3] * scale + bvec.w;
        *(float4*)(C + (size_t)row * N + col) = o;
    }
}

// Row-wise masked softmax over Lk=2048. One block (256 threads) per (b,q) row.
__global__ void __launch_bounds__(256)
softmax_mask(float* __restrict__ S, const int* __restrict__ mask)
{
    const size_t base = (size_t)blockIdx.x * SEQ;
    float*       row  = S + base;
    const int*   mrow = mask + base;
    const int tid = threadIdx.x;

    __shared__ float redmax[8];
    __shared__ float redsum[8];

    float v[8];
    float mx = -INFINITY;
    #pragma unroll
    for (int i = 0; i < 8; i++) {
        int idx = tid + i * 256;
        float s = row[idx];
        if (mrow[idx] == 0) s = -INFINITY;
        v[i] = s;
        mx = fmaxf(mx, s);
    }
    #pragma unroll
    for (int o = 16; o > 0; o >>= 1)
        mx = fmaxf(mx, __shfl_xor_sync(0xffffffffu, mx, o));
    if ((tid & 31) == 0) redmax[tid >> 5] = mx;
    __syncthreads();
    mx = redmax[0];
    #pragma unroll
    for (int w = 1; w < 8; w++) mx = fmaxf(mx, redmax[w]);

    float sum = 0.f;
    #pragma unroll
    for (int i = 0; i < 8; i++) {
        v[i] = expf(v[i] - mx);
        sum += v[i];
    }
    #pragma unroll
    for (int o = 16; o > 0; o >>= 1)
        sum += __shfl_xor_sync(0xffffffffu, sum, o);
    if ((tid & 31) == 0) redsum[tid >> 5] = sum;
    __syncthreads();
    float total = 0.f;
    #pragma unroll
    for (int w = 0; w < 8; w++) total += redsum[w];

    const float inv = 1.f / total;
    #pragma unroll
    for (int i = 0; i < 8; i++)
        row[tid + i * 256] = v[i] * inv;
}

extern "C" void kernel_launch(void* const* d_in, const int* in_sizes, int n_in,
                              void* d_out, int out_size)
{
    const float* input  = (const float*)d_in[0];
    const float* states = (const float*)d_in[1];
    const int*   mask   = (const int*)d_in[2];
    const float* wq     = (const float*)d_in[3];
    const float* bq     = (const float*)d_in[4];
    const float* wk     = (const float*)d_in[5];
    const float* bk     = (const float*)d_in[6];
    const float* wv     = (const float*)d_in[7];
    const float* bv     = (const float*)d_in[8];
    float* out = (float*)d_out;

    float *q, *k, *v, *s;
    cudaGetSymbolAddress((void**)&q, g_q);
    cudaGetSymbolAddress((void**)&k, g_k);
    cudaGetSymbolAddress((void**)&v, g_v);
    cudaGetSymbolAddress((void**)&s, g_s);

    const int M  = BATCH * SEQ;                 // 16384
    const size_t sQ = (size_t)SEQ * DIM;        // per-batch q/k/v stride
    const size_t sS = (size_t)SEQ * SEQ;        // per-batch scores stride
    const float scale = 1.0f / sqrtf((float)DIM);

    dim3 blk(256);

    // QKV projections: [16384,512] @ [512,512]^T + bias
    gemm64<true><<<dim3(DIM / BN, M / BM, 1), blk>>>(input,  wq, bq, q, M, DIM, DIM, 0, 0, 0, 1.f);
    gemm64<true><<<dim3(DIM / BN, M / BM, 1), blk>>>(states, wk, bk, k, M, DIM, DIM, 0, 0, 0, 1.f);
    gemm64<true><<<dim3(DIM / BN, M / BM, 1), blk>>>(states, wv, bv, v, M, DIM, DIM, 0, 0, 0, 1.f);

    // scores: per-batch [2048,512] @ [2048,512]^T * scale
    gemm64<true><<<dim3(SEQ / BN, SEQ / BM, BATCH), blk>>>(q, k, nullptr, s,
                                                           SEQ, SEQ, DIM, sQ, sQ, sS, scale);

    // masked softmax over key dim
    softmax_mask<<<BATCH * SEQ, 256>>>(s, mask);

    // context: per-batch [2048,2048] @ [2048,512]
    gemm64<false><<<dim3(DIM / BN, SEQ / BM, BATCH), blk>>>(s, v, nullptr, out,
                                                            SEQ, DIM, SEQ, sS, sQ, sQ, 1.f);
}

// round 4
// speedup vs baseline: 3.2442x; 3.2442x over previous
#include <cuda_runtime.h>
#include <cuda_bf16.h>
#include <cstdint>
#include <math.h>

// ---------------------------------------------------------------------------
// Attention B=8, L=2048, D=512 fp32 — bf16-split (3x mma.sync) HMMA pipeline.
// tcgen05 is unavailable (harness compiles virtual arch compute_100, no 'a'
// features), so all GEMMs use mma.sync.m16n8k16.bf16 + ldmatrix + cp.async.
//   split(inputs/weights) -> QKV gemms (split bf16 epilogue) ->
//   scores gemm (fp32, scaled) -> masked softmax (split bf16 P) ->
//   PV gemm (ldmatrix.trans on V, no V^T materialization) -> fp32 out.
// ---------------------------------------------------------------------------

#define BATCH 8
#define SEQ   2048
#define DIM   512
#define MTOT  (BATCH*SEQ)

#define KC      64
#define TILE_B  (16*1024)      // one 128x64 bf16 tile (or 64x128 for BMODE1)
#define STAGE_B (4*TILE_B)     // Ahi, Alo, Bhi, Blo
#define SMEM_TOTAL (2*STAGE_B) // 131072 B

typedef __nv_bfloat16 bf16;

// ------------------------------ scratch ------------------------------------
__device__ bf16 g_in_hi[MTOT*DIM], g_in_lo[MTOT*DIM];
__device__ bf16 g_st_hi[MTOT*DIM], g_st_lo[MTOT*DIM];
__device__ bf16 g_wq_hi[DIM*DIM], g_wq_lo[DIM*DIM];
__device__ bf16 g_wk_hi[DIM*DIM], g_wk_lo[DIM*DIM];
__device__ bf16 g_wv_hi[DIM*DIM], g_wv_lo[DIM*DIM];
__device__ bf16 g_q_hi[MTOT*DIM], g_q_lo[MTOT*DIM];
__device__ bf16 g_k_hi[MTOT*DIM], g_k_lo[MTOT*DIM];
__device__ bf16 g_v_hi[MTOT*DIM], g_v_lo[MTOT*DIM];
__device__ float g_s[(size_t)BATCH*SEQ*SEQ];
__device__ bf16 g_p_hi[(size_t)BATCH*SEQ*SEQ], g_p_lo[(size_t)BATCH*SEQ*SEQ];

// ------------------------------ helpers ------------------------------------
__device__ __forceinline__ uint32_t smem_u32(const void* p) {
    uint32_t a;
    asm("{ .reg .u64 t; cvta.to.shared.u64 t, %1; cvt.u32.u64 %0, t; }" : "=r"(a) : "l"(p));
    return a;
}
#define SW128(o) ((o) ^ (((o) >> 3) & 0x70))

__device__ __forceinline__ void cp16(uint32_t dst, const void* src) {
    asm volatile("cp.async.cg.shared.global [%0], [%1], 16;"
                 :: "r"(dst), "l"(__cvta_generic_to_global(src)) : "memory");
}
#define CP_COMMIT() asm volatile("cp.async.commit_group;" ::: "memory")

__device__ __forceinline__ void ldsm4(uint32_t* r, uint32_t addr) {
    asm volatile("ldmatrix.sync.aligned.m8n8.x4.shared.b16 {%0,%1,%2,%3}, [%4];"
                 : "=r"(r[0]), "=r"(r[1]), "=r"(r[2]), "=r"(r[3]) : "r"(addr));
}
__device__ __forceinline__ void ldsm4t(uint32_t* r, uint32_t addr) {
    asm volatile("ldmatrix.sync.aligned.m8n8.x4.trans.shared.b16 {%0,%1,%2,%3}, [%4];"
                 : "=r"(r[0]), "=r"(r[1]), "=r"(r[2]), "=r"(r[3]) : "r"(addr));
}
__device__ __forceinline__ void mma16816(float* c, const uint32_t* a,
                                         uint32_t b0, uint32_t b1) {
    asm volatile("mma.sync.aligned.m16n8k16.row.col.f32.bf16.bf16.f32 "
                 "{%0,%1,%2,%3}, {%4,%5,%6,%7}, {%8,%9}, {%0,%1,%2,%3};"
                 : "+f"(c[0]), "+f"(c[1]), "+f"(c[2]), "+f"(c[3])
                 : "r"(a[0]), "r"(a[1]), "r"(a[2]), "r"(a[3]), "r"(b0), "r"(b1));
}

// ------------------------------ split kernel -------------------------------
__global__ void __launch_bounds__(256)
splitk(const float4* __restrict__ src, __nv_bfloat162* __restrict__ hi,
       __nv_bfloat162* __restrict__ lo, int n4)
{
    int i = blockIdx.x * 256 + threadIdx.x;
    if (i >= n4) return;
    float4 v = src[i];
    bf16 h0 = __float2bfloat16(v.x), h1 = __float2bfloat16(v.y);
    bf16 h2 = __float2bfloat16(v.z), h3 = __float2bfloat16(v.w);
    bf16 l0 = __float2bfloat16(v.x - __bfloat162float(h0));
    bf16 l1 = __float2bfloat16(v.y - __bfloat162float(h1));
    bf16 l2 = __float2bfloat16(v.z - __bfloat162float(h2));
    bf16 l3 = __float2bfloat16(v.w - __bfloat162float(h3));
    hi[2*i]   = __halves2bfloat162(h0, h1);
    hi[2*i+1] = __halves2bfloat162(h2, h3);
    lo[2*i]   = __halves2bfloat162(l0, l1);
    lo[2*i+1] = __halves2bfloat162(l2, l3);
}

// ------------------------------ HMMA GEMM ----------------------------------
// C[M,N] = scale*(A @ Bop) (+bias). A = Ahi+Alo [M,K] K-major bf16.
// BMODE 0: B is [N,K] K-major (C = A @ B^T), ldmatrix non-trans.
// BMODE 1: B is [K,N] N-major (C = A @ B),   ldmatrix trans.
// EPI 0: write fp32 * scale.   EPI 1: +bias, write split bf16 hi/lo.
// Batched via blockIdx.z with element strides sA/sB/sC.
// Block 256 thr (8 warps), block tile 128x128, warp tile 64x32, K-chunk 64,
// cp.async double buffer, 3-pass split accumulate (hh + hl + lh).
template <int BMODE, int EPI>
__global__ void __launch_bounds__(256, 1)
gemm_mma(const bf16* __restrict__ Ahi_, const bf16* __restrict__ Alo_,
         const bf16* __restrict__ Bhi_, const bf16* __restrict__ Blo_,
         const float* __restrict__ bias,
         float* __restrict__ Cf, bf16* __restrict__ Chi, bf16* __restrict__ Clo,
         int M, int N, int K, long sA, long sB, long sC, float scale)
{
    extern __shared__ char smem[];
    const uint32_t sb = smem_u32(smem);
    const int tid = threadIdx.x, lane = tid & 31, wid = tid >> 5;
    const int wm = wid & 1, wn = wid >> 1;      // warp grid 2(m) x 4(n)
    const int z = blockIdx.z;

    const bf16* Ahi = Ahi_ + (long)z * sA;
    const bf16* Alo = Alo_ + (long)z * sA;
    const bf16* Bhi = Bhi_ + (long)z * sB;
    const bf16* Blo = Blo_ + (long)z * sB;

    const int m0 = blockIdx.y * 128;
    const int n0 = blockIdx.x * 128;
    const int ldB = BMODE ? N : K;
    const int nch = K / KC;

    // ---- async load of one K-chunk (4 tiles) into stage buffer ----
    auto issue = [&](int i) {
        const int k0 = i * KC;
        const uint32_t st = sb + (i & 1) * STAGE_B;
        // A hi/lo: 128 rows x 64 bf16, SW128 swizzled 128B rows
        #pragma unroll
        for (int u = 0; u < 4; u++) {
            int idx = tid + u * 256;            // 0..1023
            int r = idx >> 3, c = idx & 7;
            uint32_t off = SW128(r * 128 + c * 16);
            cp16(st + off,          Ahi + (long)(m0 + r) * K + k0 + c * 8);
            cp16(st + TILE_B + off, Alo + (long)(m0 + r) * K + k0 + c * 8);
        }
        if (BMODE == 0) {
            // B: 128 rows (n) x 64 bf16 (k)
            #pragma unroll
            for (int u = 0; u < 4; u++) {
                int idx = tid + u * 256;
                int r = idx >> 3, c = idx & 7;
                uint32_t off = SW128(r * 128 + c * 16);
                cp16(st + 2 * TILE_B + off, Bhi + (long)(n0 + r) * ldB + k0 + c * 8);
                cp16(st + 3 * TILE_B + off, Blo + (long)(n0 + r) * ldB + k0 + c * 8);
            }
        } else {
            // B: 64 rows (k) x 128 bf16 (n), stored as 2 halves of 128B rows
            #pragma unroll
            for (int u = 0; u < 4; u++) {
                int idx = tid + u * 256;
                int kk = idx >> 4, nc = idx & 15;
                uint32_t off = (uint32_t)((nc >> 3) * 8192) + SW128(kk * 128 + (nc & 7) * 16);
                cp16(st + 2 * TILE_B + off, Bhi + (long)(k0 + kk) * ldB + n0 + nc * 8);
                cp16(st + 3 * TILE_B + off, Blo + (long)(k0 + kk) * ldB + n0 + nc * 8);
            }
        }
        CP_COMMIT();
    };

    float acc[4][4][4];
    #pragma unroll
    for (int a = 0; a < 4; a++)
        #pragma unroll
        for (int b = 0; b < 4; b++)
            #pragma unroll
            for (int c = 0; c < 4; c++) acc[a][b][c] = 0.f;

    issue(0);
    issue(1);

    for (int i = 0; i < nch; i++) {
        if (i < nch - 1) asm volatile("cp.async.wait_group 1;" ::: "memory");
        else             asm volatile("cp.async.wait_group 0;" ::: "memory");
        __syncthreads();

        const uint32_t st = sb + (i & 1) * STAGE_B;
        const uint32_t sAhi = st, sAlo = st + TILE_B;
        const uint32_t sBhi = st + 2 * TILE_B, sBlo = st + 3 * TILE_B;

        #pragma unroll
        for (int ks = 0; ks < 4; ks++) {
            uint32_t ah[4][4], al[4][4], bh[2][4], bl[2][4];
            #pragma unroll
            for (int mc = 0; mc < 4; mc++) {
                int row = wm * 64 + mc * 16 + (lane & 15);
                int kb  = ks * 32 + (lane >> 4) * 16;
                uint32_t off = SW128(row * 128 + kb);
                ldsm4(ah[mc], sAhi + off);
                ldsm4(al[mc], sAlo + off);
            }
            #pragma unroll
            for (int p = 0; p < 2; p++) {
                if (BMODE == 0) {
                    int row = wn * 32 + p * 16 + ((lane >> 4) & 1) * 8 + (lane & 7);
                    int kb  = ks * 32 + ((lane >> 3) & 1) * 16;
                    uint32_t off = SW128(row * 128 + kb);
                    ldsm4(bh[p], sBhi + off);
                    ldsm4(bl[p], sBlo + off);
                } else {
                    int kk   = ks * 16 + ((lane >> 3) & 1) * 8 + (lane & 7);
                    int ncol = wn * 32 + p * 16 + ((lane >> 4) & 1) * 8;
                    uint32_t off = (uint32_t)((ncol >= 64) ? 8192 : 0)
                                 + SW128(kk * 128 + (ncol & 63) * 2);
                    ldsm4t(bh[p], sBhi + off);
                    ldsm4t(bl[p], sBlo + off);
                }
            }
            #pragma unroll
            for (int mc = 0; mc < 4; mc++)
                #pragma unroll
                for (int ng = 0; ng < 4; ng++) {
                    const uint32_t* bhp = &bh[ng >> 1][(ng & 1) * 2];
                    const uint32_t* blp = &bl[ng >> 1][(ng & 1) * 2];
                    mma16816(acc[mc][ng], ah[mc], bhp[0], bhp[1]);   // hi*hi
                    mma16816(acc[mc][ng], ah[mc], blp[0], blp[1]);   // hi*lo
                    mma16816(acc[mc][ng], al[mc], bhp[0], bhp[1]);   // lo*hi
                }
        }
        __syncthreads();
        if (i + 2 < nch) issue(i + 2);
    }

    // ---- epilogue ----
    const int g = lane >> 2, tig = lane & 3;
    #pragma unroll
    for (int mc = 0; mc < 4; mc++) {
        int row = m0 + wm * 64 + mc * 16 + g;
        #pragma unroll
        for (int ng = 0; ng < 4; ng++) {
            int col = n0 + wn * 32 + ng * 8 + tig * 2;
            float c0 = acc[mc][ng][0], c1 = acc[mc][ng][1];
            float c2 = acc[mc][ng][2], c3 = acc[mc][ng][3];
            if (EPI == 0) {
                float* Cb = Cf + (long)z * sC;
                float2 v0 = make_float2(c0 * scale, c1 * scale);
                float2 v1 = make_float2(c2 * scale, c3 * scale);
                *(float2*)(Cb + (long)row * N + col)       = v0;
                *(float2*)(Cb + (long)(row + 8) * N + col) = v1;
            } else {
                float b0 = bias[col], b1 = bias[col + 1];
                float v0 = c0 + b0, v1 = c1 + b1;
                float v2 = c2 + b0, v3 = c3 + b1;
                bf16 h0 = __float2bfloat16(v0), h1 = __float2bfloat16(v1);
                bf16 h2 = __float2bfloat16(v2), h3 = __float2bfloat16(v3);
                bf16 l0 = __float2bfloat16(v0 - __bfloat162float(h0));
                bf16 l1 = __float2bfloat16(v1 - __bfloat162float(h1));
                bf16 l2 = __float2bfloat16(v2 - __bfloat162float(h2));
                bf16 l3 = __float2bfloat16(v3 - __bfloat162float(h3));
                long o0 = (long)row * N + col, o1 = (long)(row + 8) * N + col;
                *(__nv_bfloat162*)(Chi + o0) = __halves2bfloat162(h0, h1);
                *(__nv_bfloat162*)(Chi + o1) = __halves2bfloat162(h2, h3);
                *(__nv_bfloat162*)(Clo + o0) = __halves2bfloat162(l0, l1);
                *(__nv_bfloat162*)(Clo + o1) = __halves2bfloat162(l2, l3);
            }
        }
    }
}

// ------------------------------ softmax ------------------------------------
__global__ void __launch_bounds__(256)
softmax_mask(const float* __restrict__ S, const int* __restrict__ mask,
             bf16* __restrict__ Phi, bf16* __restrict__ Plo)
{
    const size_t base = (size_t)blockIdx.x * SEQ;
    const float* row  = S + base;
    const int*   mrow = mask + base;
    const int tid = threadIdx.x;

    __shared__ float red[8];

    float v[8];
    float mx = -INFINITY;
    #pragma unroll
    for (int i = 0; i < 8; i++) {
        int idx = tid + i * 256;
        float s = row[idx];
        if (mrow[idx] == 0) s = -INFINITY;
        v[i] = s;
        mx = fmaxf(mx, s);
    }
    #pragma unroll
    for (int o = 16; o > 0; o >>= 1) mx = fmaxf(mx, __shfl_xor_sync(0xffffffffu, mx, o));
    if ((tid & 31) == 0) red[tid >> 5] = mx;
    __syncthreads();
    mx = red[0];
    #pragma unroll
    for (int w = 1; w < 8; w++) mx = fmaxf(mx, red[w]);
    __syncthreads();

    float sum = 0.f;
    #pragma unroll
    for (int i = 0; i < 8; i++) { v[i] = expf(v[i] - mx); sum += v[i]; }
    #pragma unroll
    for (int o = 16; o > 0; o >>= 1) sum += __shfl_xor_sync(0xffffffffu, sum, o);
    if ((tid & 31) == 0) red[tid >> 5] = sum;
    __syncthreads();
    float total = 0.f;
    #pragma unroll
    for (int w = 0; w < 8; w++) total += red[w];

    const float inv = 1.f / total;
    #pragma unroll
    for (int i = 0; i < 8; i++) {
        int idx = tid + i * 256;
        float p = v[i] * inv;
        bf16 h = __float2bfloat16(p);
        bf16 l = __float2bfloat16(p - __bfloat162float(h));
        Phi[base + idx] = h;
        Plo[base + idx] = l;
    }
}

// ------------------------------ launch -------------------------------------
extern "C" void kernel_launch(void* const* d_in, const int* in_sizes, int n_in,
                              void* d_out, int out_size)
{
    const float* input  = (const float*)d_in[0];
    const float* states = (const float*)d_in[1];
    const int*   mask   = (const int*)d_in[2];
    const float* wq     = (const float*)d_in[3];
    const float* bq     = (const float*)d_in[4];
    const float* wk     = (const float*)d_in[5];
    const float* bk     = (const float*)d_in[6];
    const float* wv     = (const float*)d_in[7];
    const float* bv     = (const float*)d_in[8];
    float* out = (float*)d_out;

    cudaFuncSetAttribute(gemm_mma<0,0>, cudaFuncAttributeMaxDynamicSharedMemorySize, SMEM_TOTAL);
    cudaFuncSetAttribute(gemm_mma<0,1>, cudaFuncAttributeMaxDynamicSharedMemorySize, SMEM_TOTAL);
    cudaFuncSetAttribute(gemm_mma<1,0>, cudaFuncAttributeMaxDynamicSharedMemorySize, SMEM_TOTAL);

    bf16 *in_hi, *in_lo, *st_hi, *st_lo;
    bf16 *wq_hi, *wq_lo, *wk_hi, *wk_lo, *wv_hi, *wv_lo;
    bf16 *q_hi, *q_lo, *k_hi, *k_lo, *v_hi, *v_lo, *p_hi, *p_lo;
    float* s;
    cudaGetSymbolAddress((void**)&in_hi, g_in_hi);  cudaGetSymbolAddress((void**)&in_lo, g_in_lo);
    cudaGetSymbolAddress((void**)&st_hi, g_st_hi);  cudaGetSymbolAddress((void**)&st_lo, g_st_lo);
    cudaGetSymbolAddress((void**)&wq_hi, g_wq_hi);  cudaGetSymbolAddress((void**)&wq_lo, g_wq_lo);
    cudaGetSymbolAddress((void**)&wk_hi, g_wk_hi);  cudaGetSymbolAddress((void**)&wk_lo, g_wk_lo);
    cudaGetSymbolAddress((void**)&wv_hi, g_wv_hi);  cudaGetSymbolAddress((void**)&wv_lo, g_wv_lo);
    cudaGetSymbolAddress((void**)&q_hi,  g_q_hi);   cudaGetSymbolAddress((void**)&q_lo,  g_q_lo);
    cudaGetSymbolAddress((void**)&k_hi,  g_k_hi);   cudaGetSymbolAddress((void**)&k_lo,  g_k_lo);
    cudaGetSymbolAddress((void**)&v_hi,  g_v_hi);   cudaGetSymbolAddress((void**)&v_lo,  g_v_lo);
    cudaGetSymbolAddress((void**)&p_hi,  g_p_hi);   cudaGetSymbolAddress((void**)&p_lo,  g_p_lo);
    cudaGetSymbolAddress((void**)&s, g_s);

    const float scale = 1.0f / sqrtf((float)DIM);
    const long sQK = (long)SEQ * DIM;
    const long sS  = (long)SEQ * SEQ;

    // splits (fp32 -> bf16 hi/lo)
    {
        int n4 = MTOT * DIM / 4;
        splitk<<<(n4 + 255) / 256, 256>>>((const float4*)input,  (__nv_bfloat162*)in_hi, (__nv_bfloat162*)in_lo, n4);
        splitk<<<(n4 + 255) / 256, 256>>>((const float4*)states, (__nv_bfloat162*)st_hi, (__nv_bfloat162*)st_lo, n4);
        int w4 = DIM * DIM / 4;
        splitk<<<(w4 + 255) / 256, 256>>>((const float4*)wq, (__nv_bfloat162*)wq_hi, (__nv_bfloat162*)wq_lo, w4);
        splitk<<<(w4 + 255) / 256, 256>>>((const float4*)wk, (__nv_bfloat162*)wk_hi, (__nv_bfloat162*)wk_lo, w4);
        splitk<<<(w4 + 255) / 256, 256>>>((const float4*)wv, (__nv_bfloat162*)wv_hi, (__nv_bfloat162*)wv_lo, w4);
    }

    // QKV projections: [16384,512] = A @ W^T + b  (split bf16 epilogues)
    dim3 gq(DIM / 128, MTOT / 128, 1);
    gemm_mma<0,1><<<gq, 256, SMEM_TOTAL>>>(in_hi, in_lo, wq_hi, wq_lo, bq,
                                           nullptr, q_hi, q_lo, MTOT, DIM, DIM, 0, 0, 0, 1.f);
    gemm_mma<0,1><<<gq, 256, SMEM_TOTAL>>>(st_hi, st_lo, wk_hi, wk_lo, bk,
                                           nullptr, k_hi, k_lo, MTOT, DIM, DIM, 0, 0, 0, 1.f);
    gemm_mma<0,1><<<gq, 256, SMEM_TOTAL>>>(st_hi, st_lo, wv_hi, wv_lo, bv,
                                           nullptr, v_hi, v_lo, MTOT, DIM, DIM, 0, 0, 0, 1.f);

    // scores: per-batch [2048,2048] = q @ k^T * scale (fp32)
    gemm_mma<0,0><<<dim3(SEQ / 128, SEQ / 128, BATCH), 256, SMEM_TOTAL>>>(
        q_hi, q_lo, k_hi, k_lo, nullptr, s, nullptr, nullptr,
        SEQ, SEQ, DIM, sQK, sQK, sS, scale);

    // masked softmax -> P hi/lo bf16
    softmax_mask<<<BATCH * SEQ, 256>>>(s, mask, p_hi, p_lo);

    // context: per-batch [2048,512] = P @ V   (V is [2048,512] N-major -> trans)
    gemm_mma<1,0><<<dim3(DIM / 128, SEQ / 128, BATCH), 256, SMEM_TOTAL>>>(
        p_hi, p_lo, v_hi, v_lo, nullptr, out, nullptr, nullptr,
        SEQ, DIM, SEQ, sS, sQK, sQK, 1.f);
}